// round 9
// baseline (speedup 1.0000x reference)
#include <cuda_runtime.h>
#include <cuda_fp16.h>
#include <cstdint>

#define D 128
#define GN_EPS 1e-5f
#define MAXN 50000
#define MAXE 800000
#define NPW 16          // nodes per warp in gather (8 pairs)

// ---------------- scratch ----------------
__device__ __half g_t[(size_t)MAXN * D];  // GEMM output, fp16, pre-scaled by dinv[row]
__device__ float  g_h[(size_t)MAXN * D];  // aggregated layer output (fp32)
__device__ int    g_cnt[MAXN];            // in-degree (excluding self loop)
__device__ float  g_dinv[MAXN];
__device__ int    g_rowp[MAXN];           // CSR row start
__device__ int    g_cur[MAXN];            // fill cursor
__device__ int    g_csr[MAXE];            // src ids grouped by dst
__device__ int    g_bsum[64];             // scan block totals
__device__ float  g_cs[D];
__device__ float  g_css[D];
__device__ float  g_scale[D];
__device__ float  g_shift[D];

// ---------------- degree / CSR build ----------------
__global__ void zero_cnt_k(int n) {
    int i = blockIdx.x * blockDim.x + threadIdx.x;
    if (i < n) g_cnt[i] = 0;
    if (blockIdx.x == 0 && threadIdx.x < D) {
        g_cs[threadIdx.x] = 0.0f;
        g_css[threadIdx.x] = 0.0f;
    }
}

__global__ void hist_k(const int* __restrict__ dst, int e) {
    int i = blockIdx.x * blockDim.x + threadIdx.x;
    if (i < e) atomicAdd(&g_cnt[dst[i]], 1);
}

__global__ void dinv_k(int n) {
    int i = blockIdx.x * blockDim.x + threadIdx.x;
    if (i < n) g_dinv[i] = rsqrtf((float)g_cnt[i] + 1.0f);
}

// phase 1: per-block inclusive scan of 1024-element tiles
__global__ void scan1_k(int n) {
    __shared__ int wsum[32];
    int i = blockIdx.x * 1024 + threadIdx.x;
    int lane = threadIdx.x & 31, w = threadIdx.x >> 5;
    int v = (i < n) ? g_cnt[i] : 0;
    int x = v;
#pragma unroll
    for (int off = 1; off < 32; off <<= 1) {
        int t = __shfl_up_sync(0xFFFFFFFFu, x, off);
        if (lane >= off) x += t;
    }
    if (lane == 31) wsum[w] = x;
    __syncthreads();
    if (w == 0) {
        int s = wsum[lane];
#pragma unroll
        for (int off = 1; off < 32; off <<= 1) {
            int t = __shfl_up_sync(0xFFFFFFFFu, s, off);
            if (lane >= off) s += t;
        }
        wsum[lane] = s;
    }
    __syncthreads();
    int base = (w > 0) ? wsum[w - 1] : 0;
    int excl = base + x - v;
    if (i < n) g_rowp[i] = excl;
    if (threadIdx.x == 1023) g_bsum[blockIdx.x] = base + x;
}

// phase 2: serial exclusive scan of block totals (<=64 values)
__global__ void scan2_k(int nb) {
    if (threadIdx.x == 0) {
        int run = 0;
        for (int b = 0; b < nb; b++) {
            int t = g_bsum[b];
            g_bsum[b] = run;
            run += t;
        }
    }
}

// phase 3: add block offsets
__global__ void scan3_k(int n) {
    int i = blockIdx.x * blockDim.x + threadIdx.x;
    if (i < n) {
        int r = g_rowp[i] + g_bsum[i >> 10];
        g_rowp[i] = r;
        g_cur[i] = r;
    }
}

__global__ void fill_k(const int* __restrict__ src, const int* __restrict__ dst, int e) {
    int i = blockIdx.x * blockDim.x + threadIdx.x;
    if (i < e) {
        int pos = atomicAdd(&g_cur[dst[i]], 1);
        g_csr[pos] = src[i];
    }
}

// ---------------- SGEMM: [M,128] @ [128,128] -> g_t fp16 (scaled by dinv) ----
#define BM 64
#define BK 32
__global__ void __launch_bounds__(256) gemm_k(const float* __restrict__ A,
                                              const float* __restrict__ W,
                                              int M, int transform) {
    __shared__ float xs[BM][BK + 1];
    __shared__ float ws[BK][D];
    __shared__ float s_sc[D], s_sh[D];
    const float* __restrict__ a_ptr = A ? A : g_h;

    int tid  = threadIdx.x;
    int tcol = tid & 31;
    int trow = tid >> 5;
    int row0 = blockIdx.x * BM;

    if (transform && tid < D) {
        s_sc[tid] = g_scale[tid];
        s_sh[tid] = g_shift[tid];
    }
    if (transform) __syncthreads();

    float acc[8][4];
#pragma unroll
    for (int i = 0; i < 8; i++)
#pragma unroll
        for (int j = 0; j < 4; j++) acc[i][j] = 0.0f;

    for (int kk = 0; kk < D; kk += BK) {
#pragma unroll
        for (int i = 0; i < 8; i++) {
            int idx = tid + i * 256;
            int r = idx >> 5, k = idx & 31;
            int gr = row0 + r;
            float v = (gr < M) ? a_ptr[(size_t)gr * D + kk + k] : 0.0f;
            if (transform) v = fmaxf(fmaf(v, s_sc[kk + k], s_sh[kk + k]), 0.0f);
            xs[r][k] = v;
        }
#pragma unroll
        for (int i = 0; i < 16; i++) {
            int idx = tid + i * 256;
            int k = idx >> 7, c = idx & 127;
            ws[k][c] = W[(size_t)(kk + k) * D + c];
        }
        __syncthreads();
#pragma unroll
        for (int k = 0; k < BK; k++) {
            float4 wv = *(const float4*)&ws[k][tcol * 4];
#pragma unroll
            for (int i = 0; i < 8; i++) {
                float a = xs[trow * 8 + i][k];
                acc[i][0] += a * wv.x;
                acc[i][1] += a * wv.y;
                acc[i][2] += a * wv.z;
                acc[i][3] += a * wv.w;
            }
        }
        __syncthreads();
    }
#pragma unroll
    for (int i = 0; i < 8; i++) {
        int gr = row0 + trow * 8 + i;
        if (gr < M) {
            float di = g_dinv[gr];
            __half2 h0 = __floats2half2_rn(acc[i][0] * di, acc[i][1] * di);
            __half2 h1 = __floats2half2_rn(acc[i][2] * di, acc[i][3] * di);
            uint2 o;
            o.x = *(const unsigned*)&h0;
            o.y = *(const unsigned*)&h1;
            *(uint2*)&g_t[(size_t)gr * D + tcol * 4] = o;
        }
    }
}

// ---------------- gather helpers ----------------
__device__ __forceinline__ void acc_row(float4& acc, uint2 v) {
    float2 a = __half22float2(*(const __half2*)&v.x);
    float2 c = __half22float2(*(const __half2*)&v.y);
    acc.x += a.x; acc.y += a.y; acc.z += c.x; acc.w += c.y;
}

// ---------------- CSR gather: dual-node interleaved, fp16 rows --------------
// Warp owns NPW=16 consecutive nodes as 8 pairs (d0+i, d0+8+i) processed
// CONCURRENTLY: joint batches put 16 row loads in flight; remainder phase
// keeps 2 independent loads in flight instead of a serial chain.
// MODE 0: write g_h (fp32), accumulate GraphNorm stats.
// MODE 1: fuse output head (h @ Wout + bout) -> out.
template <int MODE>
__global__ void __launch_bounds__(256) gather_k(const float* __restrict__ b,
                                                const float* __restrict__ Wout,
                                                const float* __restrict__ bout,
                                                float* __restrict__ out, int n) {
    int lane = threadIdx.x & 31;
    int warp = (blockIdx.x * blockDim.x + threadIdx.x) >> 5;
    int d0 = warp * NPW;
    if (d0 >= n) return;
    int d1 = min(d0 + NPW, n);

    float4 bb = *(const float4*)&b[lane * 4];
    float4 ssum = make_float4(0, 0, 0, 0);
    float4 ssq  = make_float4(0, 0, 0, 0);
    float w0[4], w1[4];
    float bo0 = 0.0f, bo1 = 0.0f;
    if (MODE == 1) {
#pragma unroll
        for (int j = 0; j < 4; j++) {
            w0[j] = __ldg(&Wout[(lane * 4 + j) * 2 + 0]);
            w1[j] = __ldg(&Wout[(lane * 4 + j) * 2 + 1]);
        }
        bo0 = __ldg(&bout[0]);
        bo1 = __ldg(&bout[1]);
    }

    for (int i = 0; i < 8; i++) {
        int dA = d0 + i;
        if (dA >= d1) break;
        int dB = d0 + 8 + i;
        bool hasB = (dB < d1);

        // self loops (independent loads, both issued before use)
        uint2 svA = *(const uint2*)&g_t[(size_t)dA * D + lane * 4];
        uint2 svB = hasB ? *(const uint2*)&g_t[(size_t)dB * D + lane * 4]
                         : make_uint2(0u, 0u);
        float4 accA = make_float4(0, 0, 0, 0);
        float4 accB = make_float4(0, 0, 0, 0);
        acc_row(accA, svA);
        if (hasB) acc_row(accB, svB);

        int eA = g_rowp[dA], endA = eA + g_cnt[dA];
        int eB = 0, endB = 0;
        if (hasB) { eB = g_rowp[dB]; endB = eB + g_cnt[dB]; }

        // joint 8+8 batches: 16 independent row loads in flight
        while (eA + 8 <= endA && eB + 8 <= endB) {
            int sA[8], sB[8];
#pragma unroll
            for (int j = 0; j < 8; j++) sA[j] = g_csr[eA + j];
#pragma unroll
            for (int j = 0; j < 8; j++) sB[j] = g_csr[eB + j];
            uint2 vA[8], vB[8];
#pragma unroll
            for (int j = 0; j < 8; j++)
                vA[j] = *(const uint2*)&g_t[(size_t)sA[j] * D + lane * 4];
#pragma unroll
            for (int j = 0; j < 8; j++)
                vB[j] = *(const uint2*)&g_t[(size_t)sB[j] * D + lane * 4];
#pragma unroll
            for (int j = 0; j < 8; j++) acc_row(accA, vA[j]);
#pragma unroll
            for (int j = 0; j < 8; j++) acc_row(accB, vB[j]);
            eA += 8; eB += 8;
        }
        // solo 8-batches for whichever list is longer
        while (eA + 8 <= endA) {
            int s[8];
#pragma unroll
            for (int j = 0; j < 8; j++) s[j] = g_csr[eA + j];
            uint2 v[8];
#pragma unroll
            for (int j = 0; j < 8; j++)
                v[j] = *(const uint2*)&g_t[(size_t)s[j] * D + lane * 4];
#pragma unroll
            for (int j = 0; j < 8; j++) acc_row(accA, v[j]);
            eA += 8;
        }
        while (eB + 8 <= endB) {
            int s[8];
#pragma unroll
            for (int j = 0; j < 8; j++) s[j] = g_csr[eB + j];
            uint2 v[8];
#pragma unroll
            for (int j = 0; j < 8; j++)
                v[j] = *(const uint2*)&g_t[(size_t)s[j] * D + lane * 4];
#pragma unroll
            for (int j = 0; j < 8; j++) acc_row(accB, v[j]);
            eB += 8;
        }
        // joint remainder: one edge from each per step (2 loads in flight)
        while (eA < endA && eB < endB) {
            int sa = g_csr[eA++];
            int sb = g_csr[eB++];
            uint2 va = *(const uint2*)&g_t[(size_t)sa * D + lane * 4];
            uint2 vb = *(const uint2*)&g_t[(size_t)sb * D + lane * 4];
            acc_row(accA, va);
            acc_row(accB, vb);
        }
        while (eA < endA) {
            int sa = g_csr[eA++];
            uint2 va = *(const uint2*)&g_t[(size_t)sa * D + lane * 4];
            acc_row(accA, va);
        }
        while (eB < endB) {
            int sb = g_csr[eB++];
            uint2 vb = *(const uint2*)&g_t[(size_t)sb * D + lane * 4];
            acc_row(accB, vb);
        }

        // epilogues
#pragma unroll
        for (int p = 0; p < 2; p++) {
            int d = p ? dB : dA;
            if (p && !hasB) break;
            float4 acc = p ? accB : accA;
            float di = g_dinv[d];
            acc.x = fmaf(acc.x, di, bb.x);
            acc.y = fmaf(acc.y, di, bb.y);
            acc.z = fmaf(acc.z, di, bb.z);
            acc.w = fmaf(acc.w, di, bb.w);
            if (MODE == 0) {
                *(float4*)&g_h[(size_t)d * D + lane * 4] = acc;
                ssum.x += acc.x; ssum.y += acc.y; ssum.z += acc.z; ssum.w += acc.w;
                ssq.x += acc.x * acc.x; ssq.y += acc.y * acc.y;
                ssq.z += acc.z * acc.z; ssq.w += acc.w * acc.w;
            } else {
                float a0 = acc.x * w0[0] + acc.y * w0[1] + acc.z * w0[2] + acc.w * w0[3];
                float a1 = acc.x * w1[0] + acc.y * w1[1] + acc.z * w1[2] + acc.w * w1[3];
#pragma unroll
                for (int off = 16; off > 0; off >>= 1) {
                    a0 += __shfl_down_sync(0xFFFFFFFFu, a0, off);
                    a1 += __shfl_down_sync(0xFFFFFFFFu, a1, off);
                }
                if (lane == 0) {
                    out[(size_t)d * 2 + 0] = a0 + bo0;
                    out[(size_t)d * 2 + 1] = a1 + bo1;
                }
            }
        }
    }

    if (MODE == 0) {
        atomicAdd(&g_cs[lane * 4 + 0], ssum.x);
        atomicAdd(&g_cs[lane * 4 + 1], ssum.y);
        atomicAdd(&g_cs[lane * 4 + 2], ssum.z);
        atomicAdd(&g_cs[lane * 4 + 3], ssum.w);
        atomicAdd(&g_css[lane * 4 + 0], ssq.x);
        atomicAdd(&g_css[lane * 4 + 1], ssq.y);
        atomicAdd(&g_css[lane * 4 + 2], ssq.z);
        atomicAdd(&g_css[lane * 4 + 3], ssq.w);
    }
}

// ---------------- GraphNorm finalize (also re-zeroes stats) ----------------
__global__ void finalize_k(const float* __restrict__ w, const float* __restrict__ b,
                           const float* __restrict__ a, int n) {
    int c = threadIdx.x;
    float inv_n = 1.0f / (float)n;
    float m = g_cs[c] * inv_n;
    float msq = g_css[c] * inv_n;
    float al = a[c];
    float var = msq - (2.0f * al - al * al) * m * m;
    float sc = rsqrtf(var + GN_EPS) * w[c];
    g_scale[c] = sc;
    g_shift[c] = b[c] - al * m * sc;
    g_cs[c] = 0.0f;
    g_css[c] = 0.0f;
}

// ---------------- launch ----------------
extern "C" void kernel_launch(void* const* d_in, const int* in_sizes, int n_in,
                              void* d_out, int out_size) {
    const float* x    = (const float*)d_in[0];
    const int*   ei   = (const int*)d_in[1];
    const float* W1   = (const float*)d_in[2];
    const float* b1   = (const float*)d_in[3];
    const float* W2   = (const float*)d_in[4];
    const float* b2   = (const float*)d_in[5];
    const float* W3   = (const float*)d_in[6];
    const float* b3   = (const float*)d_in[7];
    const float* gn1w = (const float*)d_in[8];
    const float* gn1b = (const float*)d_in[9];
    const float* gn1a = (const float*)d_in[10];
    const float* gn2w = (const float*)d_in[11];
    const float* gn2b = (const float*)d_in[12];
    const float* gn2a = (const float*)d_in[13];
    const float* Wout = (const float*)d_in[14];
    const float* bout = (const float*)d_in[15];

    int n = in_sizes[0] / D;
    int e = in_sizes[1] / 2;
    const int* src = ei;
    const int* dst = ei + e;

    int node_blocks = (n + 255) / 256;
    int edge_blocks = (e + 255) / 256;
    int gemm_blocks = (n + BM - 1) / BM;
    int scan_blocks = (n + 1023) / 1024;
    int gather_blocks = (n + NPW * 8 - 1) / (NPW * 8);   // one warp per NPW nodes

    // Build + layer 1 GEMM, ordered so gemm_k is our 4th launch (ncu's
    // capture slot). gemm1 only needs dinv; scan/fill only gate gather1.
    zero_cnt_k<<<node_blocks, 256>>>(n);
    hist_k<<<edge_blocks, 256>>>(dst, e);
    dinv_k<<<node_blocks, 256>>>(n);
    gemm_k<<<gemm_blocks, 256>>>(x, W1, n, 0);          // <- profiled slot
    scan1_k<<<scan_blocks, 1024>>>(n);
    scan2_k<<<1, 32>>>(scan_blocks);
    scan3_k<<<node_blocks, 256>>>(n);
    fill_k<<<edge_blocks, 256>>>(src, dst, e);

    // ---- layer 1 aggregation ----
    gather_k<0><<<gather_blocks, 256>>>(b1, nullptr, nullptr, nullptr, n);
    finalize_k<<<1, 128>>>(gn1w, gn1b, gn1a, n);

    // ---- layer 2 ----
    gemm_k<<<gemm_blocks, 256>>>(nullptr, W2, n, 1);
    gather_k<0><<<gather_blocks, 256>>>(b2, nullptr, nullptr, nullptr, n);
    finalize_k<<<1, 128>>>(gn2w, gn2b, gn2a, n);

    // ---- layer 3 ----
    gemm_k<<<gemm_blocks, 256>>>(nullptr, W3, n, 1);
    gather_k<1><<<gather_blocks, 256>>>(b3, Wout, bout, (float*)d_out, n);
}

// round 12
// speedup vs baseline: 1.1067x; 1.1067x over previous
#include <cuda_runtime.h>
#include <cuda_fp16.h>
#include <mma.h>
#include <cstdint>

using namespace nvcuda;

#define D 128
#define GN_EPS 1e-5f
#define MAXN 50000
#define MAXE 800000
#define NPW 16          // nodes per warp in gather

// ---------------- scratch ----------------
__device__ __half g_t[(size_t)MAXN * D];  // GEMM output, fp16, pre-scaled by dinv[row]
__device__ float  g_h[(size_t)MAXN * D];  // aggregated layer output (fp32)
__device__ int    g_cnt[MAXN];
__device__ float  g_dinv[MAXN];
__device__ int    g_rowp[MAXN];
__device__ int    g_cur[MAXN];
__device__ int    g_csr[MAXE];
__device__ int    g_bsum[64];
__device__ float  g_cs[D];
__device__ float  g_css[D];
__device__ float  g_scale[D];
__device__ float  g_shift[D];

// ---------------- degree / CSR build ----------------
__global__ void zero_cnt_k(int n) {
    int i = blockIdx.x * blockDim.x + threadIdx.x;
    if (i < n) g_cnt[i] = 0;
    if (blockIdx.x == 0 && threadIdx.x < D) {
        g_cs[threadIdx.x] = 0.0f;
        g_css[threadIdx.x] = 0.0f;
    }
}

__global__ void hist_k(const int* __restrict__ dst, int e) {
    int i = blockIdx.x * blockDim.x + threadIdx.x;
    if (i < e) atomicAdd(&g_cnt[dst[i]], 1);
}

__global__ void dinv_k(int n) {
    int i = blockIdx.x * blockDim.x + threadIdx.x;
    if (i < n) g_dinv[i] = rsqrtf((float)g_cnt[i] + 1.0f);
}

__global__ void scan1_k(int n) {
    __shared__ int wsum[32];
    int i = blockIdx.x * 1024 + threadIdx.x;
    int lane = threadIdx.x & 31, w = threadIdx.x >> 5;
    int v = (i < n) ? g_cnt[i] : 0;
    int x = v;
#pragma unroll
    for (int off = 1; off < 32; off <<= 1) {
        int t = __shfl_up_sync(0xFFFFFFFFu, x, off);
        if (lane >= off) x += t;
    }
    if (lane == 31) wsum[w] = x;
    __syncthreads();
    if (w == 0) {
        int s = wsum[lane];
#pragma unroll
        for (int off = 1; off < 32; off <<= 1) {
            int t = __shfl_up_sync(0xFFFFFFFFu, s, off);
            if (lane >= off) s += t;
        }
        wsum[lane] = s;
    }
    __syncthreads();
    int base = (w > 0) ? wsum[w - 1] : 0;
    int excl = base + x - v;
    if (i < n) g_rowp[i] = excl;
    if (threadIdx.x == 1023) g_bsum[blockIdx.x] = base + x;
}

__global__ void scan2_k(int nb) {
    if (threadIdx.x == 0) {
        int run = 0;
        for (int b = 0; b < nb; b++) {
            int t = g_bsum[b];
            g_bsum[b] = run;
            run += t;
        }
    }
}

__global__ void scan3_k(int n) {
    int i = blockIdx.x * blockDim.x + threadIdx.x;
    if (i < n) {
        int r = g_rowp[i] + g_bsum[i >> 10];
        g_rowp[i] = r;
        g_cur[i] = r;
    }
}

__global__ void fill_k(const int* __restrict__ src, const int* __restrict__ dst, int e) {
    int i = blockIdx.x * blockDim.x + threadIdx.x;
    if (i < e) {
        int pos = atomicAdd(&g_cur[dst[i]], 1);
        g_csr[pos] = src[i];
    }
}

// ---------------- Tensor-core GEMM with Markidis fp16 split -----------------
// D = (Ah+Al)(Bh+Bl) ~= Ah*Bh + Ah*Bl + Al*Bh  (fp32 accum, ~fp32-exact)
// Block: 256 thr (8 warps), tile 128 rows x 128 cols, K chunked by 64.
// A == nullptr: read g_h with fused norm scale/shift + relu.
// Epilogue: acc * dinv[row] -> fp16 g_t.
#define GBM 128
#define AH_OFF 0
#define AL_OFF 18432            // 128*72*2
#define BH_OFF 36864
#define BL_OFF 54272            // + 64*136*2
#define SC_OFF 71680
#define GEMM_SMEM 81920         // + 8*16*20*4

__global__ void __launch_bounds__(256) gemm_tc_k(const float* __restrict__ A,
                                                 const float* __restrict__ W,
                                                 int M, int transform) {
    extern __shared__ char sm[];
    __half* AH = (__half*)(sm + AH_OFF);   // [128][72]
    __half* AL = (__half*)(sm + AL_OFF);
    __half* BH = (__half*)(sm + BH_OFF);   // [64][136]
    __half* BL = (__half*)(sm + BL_OFF);
    float*  SC = (float*)(sm + SC_OFF);    // [8][16][20]

    const float* __restrict__ a_ptr = A ? A : g_h;
    int tid  = threadIdx.x;
    int warp = tid >> 5, lane = tid & 31;
    int row0 = blockIdx.x * GBM;

    wmma::fragment<wmma::accumulator, 16, 16, 16, float> acc[8];
#pragma unroll
    for (int n = 0; n < 8; n++) wmma::fill_fragment(acc[n], 0.0f);

    for (int kc = 0; kc < D; kc += 64) {
        // A chunk 128x64 (fp32 -> hi/lo fp16), transform fused
        for (int i = tid; i < 128 * 64; i += 256) {
            int r = i >> 6, k = i & 63;
            int gr = row0 + r, gk = kc + k;
            float v = (gr < M) ? a_ptr[(size_t)gr * D + gk] : 0.0f;
            if (transform) v = fmaxf(fmaf(v, g_scale[gk], g_shift[gk]), 0.0f);
            __half hi = __float2half_rn(v);
            __half lo = __float2half_rn(v - __half2float(hi));
            AH[r * 72 + k] = hi;
            AL[r * 72 + k] = lo;
        }
        // B chunk 64x128 from W rows kc..kc+63
        for (int i = tid; i < 64 * 128; i += 256) {
            int r = i >> 7, c = i & 127;
            float v = W[(size_t)(kc + r) * D + c];
            __half hi = __float2half_rn(v);
            __half lo = __float2half_rn(v - __half2float(hi));
            BH[r * 136 + c] = hi;
            BL[r * 136 + c] = lo;
        }
        __syncthreads();

#pragma unroll
        for (int ks = 0; ks < 4; ks++) {
            wmma::fragment<wmma::matrix_a, 16, 16, 16, __half, wmma::row_major> ah, al;
            wmma::load_matrix_sync(ah, AH + (warp * 16) * 72 + ks * 16, 72);
            wmma::load_matrix_sync(al, AL + (warp * 16) * 72 + ks * 16, 72);
#pragma unroll
            for (int n = 0; n < 8; n++) {
                wmma::fragment<wmma::matrix_b, 16, 16, 16, __half, wmma::row_major> bh, bl;
                wmma::load_matrix_sync(bh, BH + (ks * 16) * 136 + n * 16, 136);
                wmma::load_matrix_sync(bl, BL + (ks * 16) * 136 + n * 16, 136);
                wmma::mma_sync(acc[n], ah, bh, acc[n]);
                wmma::mma_sync(acc[n], ah, bl, acc[n]);
                wmma::mma_sync(acc[n], al, bh, acc[n]);
            }
        }
        __syncthreads();
    }

    // epilogue: acc -> *dinv -> fp16 g_t
    float* mysc = SC + warp * (16 * 20);
#pragma unroll
    for (int n = 0; n < 8; n++) {
        wmma::store_matrix_sync(mysc, acc[n], 20, wmma::mem_row_major);
        __syncwarp();
#pragma unroll
        for (int q = 0; q < 2; q++) {
            int slot = lane + q * 32;            // 0..63
            int r = slot >> 2, quad = slot & 3;
            int gr = row0 + warp * 16 + r;
            if (gr < M) {
                float di = g_dinv[gr];
                float v0 = mysc[r * 20 + quad * 4 + 0] * di;
                float v1 = mysc[r * 20 + quad * 4 + 1] * di;
                float v2 = mysc[r * 20 + quad * 4 + 2] * di;
                float v3 = mysc[r * 20 + quad * 4 + 3] * di;
                __half2 h0 = __floats2half2_rn(v0, v1);
                __half2 h1 = __floats2half2_rn(v2, v3);
                uint2 o;
                o.x = *(const unsigned*)&h0;
                o.y = *(const unsigned*)&h1;
                *(uint2*)&g_t[(size_t)gr * D + n * 16 + quad * 4] = o;
            }
        }
        __syncwarp();
    }
}

// ---------------- CSR gather (best variant: simple fp16, NPW nodes/warp) -----
template <int MODE>
__global__ void __launch_bounds__(256) gather_k(const float* __restrict__ b,
                                                const float* __restrict__ Wout,
                                                const float* __restrict__ bout,
                                                float* __restrict__ out, int n) {
    int lane = threadIdx.x & 31;
    int warp = (blockIdx.x * blockDim.x + threadIdx.x) >> 5;
    int d0 = warp * NPW;
    if (d0 >= n) return;
    int d1 = min(d0 + NPW, n);

    float4 bb = *(const float4*)&b[lane * 4];
    float4 ssum = make_float4(0, 0, 0, 0);
    float4 ssq  = make_float4(0, 0, 0, 0);
    float w0[4], w1[4];
    float bo0 = 0.0f, bo1 = 0.0f;
    if (MODE == 1) {
#pragma unroll
        for (int j = 0; j < 4; j++) {
            w0[j] = __ldg(&Wout[(lane * 4 + j) * 2 + 0]);
            w1[j] = __ldg(&Wout[(lane * 4 + j) * 2 + 1]);
        }
        bo0 = __ldg(&bout[0]);
        bo1 = __ldg(&bout[1]);
    }

    for (int d = d0; d < d1; d++) {
        uint2 sr = *(const uint2*)&g_t[(size_t)d * D + lane * 4];
        float2 s0f = __half22float2(*(const __half2*)&sr.x);
        float2 s1f = __half22float2(*(const __half2*)&sr.y);
        float4 acc = make_float4(s0f.x, s0f.y, s1f.x, s1f.y);

        int beg = g_rowp[d];
        int end = beg + g_cnt[d];
        int e = beg;
        for (; e + 8 <= end; e += 8) {
            int s[8];
#pragma unroll
            for (int j = 0; j < 8; j++) s[j] = g_csr[e + j];
            uint2 v[8];
#pragma unroll
            for (int j = 0; j < 8; j++)
                v[j] = *(const uint2*)&g_t[(size_t)s[j] * D + lane * 4];
#pragma unroll
            for (int j = 0; j < 8; j++) {
                float2 a = __half22float2(*(const __half2*)&v[j].x);
                float2 c = __half22float2(*(const __half2*)&v[j].y);
                acc.x += a.x; acc.y += a.y; acc.z += c.x; acc.w += c.y;
            }
        }
        for (; e < end; e++) {
            int s = g_csr[e];
            uint2 vv = *(const uint2*)&g_t[(size_t)s * D + lane * 4];
            float2 a = __half22float2(*(const __half2*)&vv.x);
            float2 c = __half22float2(*(const __half2*)&vv.y);
            acc.x += a.x; acc.y += a.y; acc.z += c.x; acc.w += c.y;
        }
        float di = g_dinv[d];
        acc.x = fmaf(acc.x, di, bb.x);
        acc.y = fmaf(acc.y, di, bb.y);
        acc.z = fmaf(acc.z, di, bb.z);
        acc.w = fmaf(acc.w, di, bb.w);

        if (MODE == 0) {
            *(float4*)&g_h[(size_t)d * D + lane * 4] = acc;
            ssum.x += acc.x; ssum.y += acc.y; ssum.z += acc.z; ssum.w += acc.w;
            ssq.x += acc.x * acc.x; ssq.y += acc.y * acc.y;
            ssq.z += acc.z * acc.z; ssq.w += acc.w * acc.w;
        } else {
            float a0 = acc.x * w0[0] + acc.y * w0[1] + acc.z * w0[2] + acc.w * w0[3];
            float a1 = acc.x * w1[0] + acc.y * w1[1] + acc.z * w1[2] + acc.w * w1[3];
#pragma unroll
            for (int off = 16; off > 0; off >>= 1) {
                a0 += __shfl_down_sync(0xFFFFFFFFu, a0, off);
                a1 += __shfl_down_sync(0xFFFFFFFFu, a1, off);
            }
            if (lane == 0) {
                out[(size_t)d * 2 + 0] = a0 + bo0;
                out[(size_t)d * 2 + 1] = a1 + bo1;
            }
        }
    }

    if (MODE == 0) {
        atomicAdd(&g_cs[lane * 4 + 0], ssum.x);
        atomicAdd(&g_cs[lane * 4 + 1], ssum.y);
        atomicAdd(&g_cs[lane * 4 + 2], ssum.z);
        atomicAdd(&g_cs[lane * 4 + 3], ssum.w);
        atomicAdd(&g_css[lane * 4 + 0], ssq.x);
        atomicAdd(&g_css[lane * 4 + 1], ssq.y);
        atomicAdd(&g_css[lane * 4 + 2], ssq.z);
        atomicAdd(&g_css[lane * 4 + 3], ssq.w);
    }
}

// ---------------- GraphNorm finalize (also re-zeroes stats) ----------------
__global__ void finalize_k(const float* __restrict__ w, const float* __restrict__ b,
                           const float* __restrict__ a, int n) {
    int c = threadIdx.x;
    float inv_n = 1.0f / (float)n;
    float m = g_cs[c] * inv_n;
    float msq = g_css[c] * inv_n;
    float al = a[c];
    float var = msq - (2.0f * al - al * al) * m * m;
    float sc = rsqrtf(var + GN_EPS) * w[c];
    g_scale[c] = sc;
    g_shift[c] = b[c] - al * m * sc;
    g_cs[c] = 0.0f;
    g_css[c] = 0.0f;
}

// ---------------- launch ----------------
extern "C" void kernel_launch(void* const* d_in, const int* in_sizes, int n_in,
                              void* d_out, int out_size) {
    const float* x    = (const float*)d_in[0];
    const int*   ei   = (const int*)d_in[1];
    const float* W1   = (const float*)d_in[2];
    const float* b1   = (const float*)d_in[3];
    const float* W2   = (const float*)d_in[4];
    const float* b2   = (const float*)d_in[5];
    const float* W3   = (const float*)d_in[6];
    const float* b3   = (const float*)d_in[7];
    const float* gn1w = (const float*)d_in[8];
    const float* gn1b = (const float*)d_in[9];
    const float* gn1a = (const float*)d_in[10];
    const float* gn2w = (const float*)d_in[11];
    const float* gn2b = (const float*)d_in[12];
    const float* gn2a = (const float*)d_in[13];
    const float* Wout = (const float*)d_in[14];
    const float* bout = (const float*)d_in[15];

    int n = in_sizes[0] / D;
    int e = in_sizes[1] / 2;
    const int* src = ei;
    const int* dst = ei + e;

    int node_blocks = (n + 255) / 256;
    int edge_blocks = (e + 255) / 256;
    int gemm_blocks = (n + GBM - 1) / GBM;
    int scan_blocks = (n + 1023) / 1024;
    int gather_blocks = (n + NPW * 8 - 1) / (NPW * 8);

    static bool attr_set = false;
    if (!attr_set) {
        cudaFuncSetAttribute(gemm_tc_k, cudaFuncAttributeMaxDynamicSharedMemorySize,
                             GEMM_SMEM);
        attr_set = true;
    }

    // Build + layer 1 GEMM (gemm at launch index 3 = ncu capture slot)
    zero_cnt_k<<<node_blocks, 256>>>(n);
    hist_k<<<edge_blocks, 256>>>(dst, e);
    dinv_k<<<node_blocks, 256>>>(n);
    gemm_tc_k<<<gemm_blocks, 256, GEMM_SMEM>>>(x, W1, n, 0);   // <- profiled
    scan1_k<<<scan_blocks, 1024>>>(n);
    scan2_k<<<1, 32>>>(scan_blocks);
    scan3_k<<<node_blocks, 256>>>(n);
    fill_k<<<edge_blocks, 256>>>(src, dst, e);

    // ---- layer 1 aggregation ----
    gather_k<0><<<gather_blocks, 256>>>(b1, nullptr, nullptr, nullptr, n);
    finalize_k<<<1, 128>>>(gn1w, gn1b, gn1a, n);

    // ---- layer 2 ----
    gemm_tc_k<<<gemm_blocks, 256, GEMM_SMEM>>>(nullptr, W2, n, 1);
    gather_k<0><<<gather_blocks, 256>>>(b2, nullptr, nullptr, nullptr, n);
    finalize_k<<<1, 128>>>(gn2w, gn2b, gn2a, n);

    // ---- layer 3 ----
    gemm_tc_k<<<gemm_blocks, 256, GEMM_SMEM>>>(nullptr, W3, n, 1);
    gather_k<1><<<gather_blocks, 256>>>(b3, Wout, bout, (float*)d_out, n);
}